// round 13
// baseline (speedup 1.0000x reference)
#include <cuda_runtime.h>

#define BB 32
#define NN 65536
#define MM 64

#define BINS 16
#define NBIN (BINS * BINS)
#define BINW_INV 0.025f      // 1/40px
#define EXPAND 36.0f         // max pred half-extent (w < 72)
#define GTCAP 64             // list cap = MM, cannot overflow

static __device__ unsigned long long g_colmax[BB * MM];
static __device__ float g_acc[BB][4];                 // cls_sum, reg_sum, vcnt, pcnt
static __device__ int g_bincnt[BB * NBIN];
static __device__ unsigned char g_bingt[BB * NBIN * GTCAP];

#define POS_THR 0.5f
#define NEG_THR 0.4f
#define SCAT_THR 0.1f
#define ALPHA_C 0.25f
#define BBOX_W 2.0f
#define EPSI 1e-6f

// ---------------- KIB: fused init + per-bin gt lists (one block per image; R9 version) ----------------
__global__ __launch_bounds__(NBIN)
void kib_init_bins(const float* __restrict__ gt) {
    int img = blockIdx.x;
    int tid = threadIdx.x;   // 256

    g_bincnt[img * NBIN + tid] = 0;
    if (tid < MM) g_colmax[img * MM + tid] = 0ull;
    if (tid < 4) g_acc[img][tid] = 0.0f;
    __syncthreads();

    if (tid < MM) {
        const float* g = gt + ((size_t)img * MM + tid) * 4;
        float gx1 = g[0], gy1 = g[1], gx2 = g[2], gy2 = g[3];
        int bx0 = max(0, (int)floorf((gx1 - EXPAND) * BINW_INV));
        int bx1 = min(BINS - 1, (int)floorf((gx2 + EXPAND) * BINW_INV));
        int by0 = max(0, (int)floorf((gy1 - EXPAND) * BINW_INV));
        int by1 = min(BINS - 1, (int)floorf((gy2 + EXPAND) * BINW_INV));
        for (int by = by0; by <= by1; by++)
            for (int bx = bx0; bx <= bx1; bx++) {
                int bin = img * NBIN + by * BINS + bx;
                int slot = atomicAdd(&g_bincnt[bin], 1);
                g_bingt[(size_t)bin * GTCAP + slot] = (unsigned char)tid;
            }
    }
}

// R8-identical focal
__device__ __forceinline__ float focal_term(float l, bool pos) {
    float t = pos ? 1.0f : 0.0f;
    float bce = fmaxf(l, 0.0f) - l * t + __logf(1.0f + __expf(-fabsf(l)));
    float pp = __fdividef(1.0f, 1.0f + __expf(-l));
    float p_t = pos ? pp : 1.0f - pp;
    float a_t = pos ? ALPHA_C : 1.0f - ALPHA_C;
    float om = 1.0f - p_t;
    return a_t * om * om * bce;
}

__device__ __forceinline__ float giou_term(float x1, float y1, float x2, float y2,
                                           float gx1, float gy1, float gx2, float gy2) {
    float ix1 = fmaxf(x1, gx1), iy1 = fmaxf(y1, gy1);
    float ix2 = fminf(x2, gx2), iy2 = fminf(y2, gy2);
    float inter = fmaxf(ix2 - ix1, 0.0f) * fmaxf(iy2 - iy1, 0.0f);
    float ap = (x2 - x1) * (y2 - y1);
    float ag = (gx2 - gx1) * (gy2 - gy1);
    float uni = ap + ag - inter;
    float iou = __fdividef(inter, fmaxf(uni, EPSI));
    float ex1 = fminf(x1, gx1), ey1 = fminf(y1, gy1);
    float ex2 = fmaxf(x2, gx2), ey2 = fmaxf(y2, gy2);
    float enc = (ex2 - ex1) * (ey2 - ey1);
    float giou = iou - __fdividef(enc - uni, fmaxf(enc, EPSI));
    return 1.0f - giou;
}

// ---------------- KB: main pass (R8 internals + smem-staged pred records) ----------------
#define KB_THREADS 256
#define KB_T 8

__global__ __launch_bounds__(KB_THREADS)
void kb_main(const float* __restrict__ pred, const float* __restrict__ gt) {
    __shared__ float sgx1[MM], sgy1[MM], sgx2[MM], sgy2[MM], sga[MM];
    __shared__ unsigned long long shcol[MM];
    __shared__ float red[4][8];
    __shared__ float stage[2][KB_THREADS * 5];   // double-buffered pred records

    const int img = blockIdx.y;
    const int tid = threadIdx.x;

    if (tid < MM) {
        const float* g = gt + ((size_t)img * MM + tid) * 4;
        float x1 = g[0], y1 = g[1], x2 = g[2], y2 = g[3];
        sgx1[tid] = x1; sgy1[tid] = y1; sgx2[tid] = x2; sgy2[tid] = y2;
        sga[tid] = (x2 - x1) * (y2 - y1);
        shcol[tid] = 0ull;
    }
    __syncthreads();

    const int base = blockIdx.x * (KB_THREADS * KB_T);
    float s_cls = 0.0f, s_reg = 0.0f, c_v = 0.0f, c_p = 0.0f;

    for (int k = 0; k < KB_T; k++) {
        // cooperative coalesced stage of 256 pred records (1280 consecutive floats)
        float* buf = stage[k & 1];
        const float* gsrc = pred + ((size_t)img * NN + base + k * KB_THREADS) * 5;
#pragma unroll
        for (int f = 0; f < 5; f++)
            buf[tid + f * KB_THREADS] = gsrc[tid + f * KB_THREADS];
        __syncthreads();   // buf[k&1] was last read 2 iters ago; all threads past those reads

        int idx = base + k * KB_THREADS + tid;
        float cx = buf[tid * 5 + 0], cy = buf[tid * 5 + 1];
        float w  = buf[tid * 5 + 2], h  = buf[tid * 5 + 3];
        float l  = buf[tid * 5 + 4];
        float x1 = cx - 0.5f * w, y1 = cy - 0.5f * h;
        float x2 = cx + 0.5f * w, y2 = cy + 0.5f * h;
        float pa = (x2 - x1) * (y2 - y1);

        int bx = min(BINS - 1, (int)(cx * BINW_INV));
        int by = min(BINS - 1, (int)(cy * BINW_INV));
        int bin = img * NBIN + by * BINS + bx;
        int cnt = g_bincnt[bin];
        const unsigned char* lst = g_bingt + (size_t)bin * GTCAP;

        float bv = 0.0f; int bj = 0;
        for (int t0 = 0; t0 < cnt; t0 += 8) {
            unsigned long long pk = *(const unsigned long long*)(lst + t0);
            int lim = min(8, cnt - t0);
            for (int tt = 0; tt < lim; tt++) {
                int j = (int)((pk >> (8 * tt)) & 0xFFull);
                float ix1 = fmaxf(x1, sgx1[j]), iy1 = fmaxf(y1, sgy1[j]);
                float ix2 = fminf(x2, sgx2[j]), iy2 = fminf(y2, sgy2[j]);
                float inter = fmaxf(ix2 - ix1, 0.0f) * fmaxf(iy2 - iy1, 0.0f);
                float uni = pa + sga[j] - inter;
                float iou = __fdividef(inter, fmaxf(uni, EPSI));
                if (iou > bv || (iou == bv && j < bj)) { bv = iou; bj = j; }
                if (iou > SCAT_THR) {
                    unsigned long long key =
                        ((unsigned long long)__float_as_uint(iou) << 32) |
                        (0xFFFFFFFFu - (unsigned int)idx);
                    atomicMax(&shcol[j], key);
                }
            }
        }

        bool pos = bv > POS_THR;
        bool neg = bv < NEG_THR;
        bool valid = pos || neg;
        float fl = focal_term(l, pos);
        float gterm = giou_term(x1, y1, x2, y2,
                                sgx1[bj], sgy1[bj], sgx2[bj], sgy2[bj]);
        s_cls += valid ? fl : 0.0f;
        s_reg += pos ? gterm : 0.0f;
        c_v   += valid ? 1.0f : 0.0f;
        c_p   += pos ? 1.0f : 0.0f;
    }

#pragma unroll
    for (int off = 16; off; off >>= 1) {
        s_cls += __shfl_down_sync(0xFFFFFFFFu, s_cls, off);
        s_reg += __shfl_down_sync(0xFFFFFFFFu, s_reg, off);
        c_v   += __shfl_down_sync(0xFFFFFFFFu, c_v, off);
        c_p   += __shfl_down_sync(0xFFFFFFFFu, c_p, off);
    }
    int wid = tid >> 5, lid = tid & 31;
    if (lid == 0) { red[0][wid] = s_cls; red[1][wid] = s_reg; red[2][wid] = c_v; red[3][wid] = c_p; }
    __syncthreads();
    if (tid < MM) {
        unsigned long long v = shcol[tid];
        if (v) atomicMax(&g_colmax[img * MM + tid], v);
    }
    if (tid == 0) {
        float a = 0, b = 0, c = 0, d = 0;
#pragma unroll
        for (int i = 0; i < 8; i++) { a += red[0][i]; b += red[1][i]; c += red[2][i]; d += red[3][i]; }
        atomicAdd(&g_acc[img][0], a);
        atomicAdd(&g_acc[img][1], b);
        atomicAdd(&g_acc[img][2], c);
        atomicAdd(&g_acc[img][3], d);
    }
}

// ---------------- K2: scatter fixup (R8-identical) ----------------
__global__ void k2_fixup(const float* __restrict__ pred, const float* __restrict__ gt) {
    __shared__ int s_pred[MM];
    __shared__ int s_gate[MM];

    int img = blockIdx.x;
    int j = threadIdx.x;   // 64 threads

    unsigned long long v = g_colmax[img * MM + j];
    float val = __uint_as_float((unsigned int)(v >> 32));
    unsigned int pidx = 0xFFFFFFFFu - (unsigned int)(v & 0xFFFFFFFFull);
    int gate = (val > SCAT_THR && pidx < NN) ? 1 : 0;
    s_pred[j] = (int)pidx;
    s_gate[j] = gate;
    __syncthreads();

    bool mine = gate;
    if (gate) {
        for (int q = 0; q < j; q++)
            if (s_gate[q] && s_pred[q] == (int)pidx) { mine = false; break; }
    }
    if (!mine) return;

    int i = (int)pidx;
    const float* p = pred + ((size_t)img * NN + i) * 5;
    float cx = p[0], cy = p[1], w = p[2], h = p[3], l = p[4];
    float x1 = cx - 0.5f * w, y1 = cy - 0.5f * h;
    float x2 = cx + 0.5f * w, y2 = cy + 0.5f * h;
    float pa = (x2 - x1) * (y2 - y1);

    int bx = min(BINS - 1, (int)(cx * BINW_INV));
    int by = min(BINS - 1, (int)(cy * BINW_INV));
    int bin = img * NBIN + by * BINS + bx;
    int cnt = g_bincnt[bin];
    const unsigned char* lst = g_bingt + (size_t)bin * GTCAP;
    const float* gbase = gt + (size_t)img * MM * 4;
    float bv = 0.0f; int bj = 0;
    for (int t0 = 0; t0 < cnt; t0 += 8) {
        unsigned long long pk = *(const unsigned long long*)(lst + t0);
        int lim = min(8, cnt - t0);
        for (int tt = 0; tt < lim; tt++) {
            int jj = (int)((pk >> (8 * tt)) & 0xFFull);
            const float* g = gbase + jj * 4;
            float gx1 = g[0], gy1 = g[1], gx2 = g[2], gy2 = g[3];
            float ix1 = fmaxf(x1, gx1), iy1 = fmaxf(y1, gy1);
            float ix2 = fminf(x2, gx2), iy2 = fminf(y2, gy2);
            float inter = fmaxf(ix2 - ix1, 0.0f) * fmaxf(iy2 - iy1, 0.0f);
            float uni = pa + (gx2 - gx1) * (gy2 - gy1) - inter;
            float iou = __fdividef(inter, fmaxf(uni, EPSI));
            if (iou > bv || (iou == bv && jj < bj)) { bv = iou; bj = jj; }
        }
    }

    bool pos0 = bv > POS_THR;
    if (pos0) return;

    bool neg = bv < NEG_THR;
    float fl1 = focal_term(l, true);
    float fl0 = focal_term(l, false);
    const float* gm = gbase + bj * 4;
    float gterm = giou_term(x1, y1, x2, y2, gm[0], gm[1], gm[2], gm[3]);

    float d_cls = fl1 - (neg ? fl0 : 0.0f);
    float d_v   = neg ? 0.0f : 1.0f;
    atomicAdd(&g_acc[img][0], d_cls);
    atomicAdd(&g_acc[img][1], gterm);
    atomicAdd(&g_acc[img][2], d_v);
    atomicAdd(&g_acc[img][3], 1.0f);
}

// ---------------- K4: final scalar (R8-identical) ----------------
__global__ void k4_final(float* __restrict__ out) {
    int tid = threadIdx.x;  // 32 threads = BB images
    float sc = g_acc[tid][0], sr = g_acc[tid][1];
    float vc = g_acc[tid][2], pc = g_acc[tid][3];
    float cls = (vc > 0.0f) ? sc / fmaxf(vc, 1.0f) : 0.0f;
    float reg = (pc > 0.0f) ? sr / fmaxf(pc, 1.0f) : 0.0f;
    float np = pc;
#pragma unroll
    for (int off = 16; off; off >>= 1) {
        cls += __shfl_down_sync(0xFFFFFFFFu, cls, off);
        reg += __shfl_down_sync(0xFFFFFFFFu, reg, off);
        np  += __shfl_down_sync(0xFFFFFFFFu, np, off);
    }
    if (tid == 0) {
        float num_pos = fmaxf(np, 1.0f);
        out[0] = cls / (float)BB + BBOX_W * (reg / num_pos * (float)BB);
    }
}

extern "C" void kernel_launch(void* const* d_in, const int* in_sizes, int n_in,
                              void* d_out, int out_size) {
    const float* pred = (const float*)d_in[0];  // [B, N, 5]
    const float* gt   = (const float*)d_in[1];  // [B, M, 4]
    float* out = (float*)d_out;

    kib_init_bins<<<BB, NBIN>>>(gt);
    dim3 gb(NN / (KB_THREADS * KB_T), BB);
    kb_main<<<gb, KB_THREADS>>>(pred, gt);
    k2_fixup<<<BB, MM>>>(pred, gt);
    k4_final<<<1, 32>>>(out);
}

// round 14
// speedup vs baseline: 1.3366x; 1.3366x over previous
#include <cuda_runtime.h>

#define BB 32
#define NN 65536
#define MM 64

#define BINS 32
#define NBIN (BINS * BINS)
#define BINW_INV 0.05f       // 1/20px
#define EXPAND 36.0f         // max pred half-extent (w < 72)
#define GTCAP 64             // list cap = MM, cannot overflow

static __device__ unsigned long long g_colmax[BB * MM];
static __device__ float g_acc[BB][4];                 // cls_sum, reg_sum, vcnt, pcnt
static __device__ int g_bincnt[BB * NBIN];
static __device__ unsigned char g_bingt[BB * NBIN * GTCAP];

#define POS_THR 0.5f
#define NEG_THR 0.4f
#define SCAT_THR 0.1f
#define ALPHA_C 0.25f
#define BBOX_W 2.0f
#define EPSI 1e-6f

// ---------------- K0: init scratch (R8 pattern, grid scaled to NBIN) ----------------
__global__ void k0_init() {
    int i = blockIdx.x * blockDim.x + threadIdx.x;   // BB*NBIN threads
    g_bincnt[i] = 0;
    if (i < BB * MM) g_colmax[i] = 0ull;
    if (i < BB * 4) ((float*)g_acc)[i] = 0.0f;
}

// ---------------- KA: per-bin gt lists (R8-identical logic) ----------------
__global__ void ka_bins(const float* __restrict__ gt) {
    int img = blockIdx.x;
    int j = threadIdx.x;  // 64 threads = gts
    const float* g = gt + ((size_t)img * MM + j) * 4;
    float gx1 = g[0], gy1 = g[1], gx2 = g[2], gy2 = g[3];
    int bx0 = max(0, (int)floorf((gx1 - EXPAND) * BINW_INV));
    int bx1 = min(BINS - 1, (int)floorf((gx2 + EXPAND) * BINW_INV));
    int by0 = max(0, (int)floorf((gy1 - EXPAND) * BINW_INV));
    int by1 = min(BINS - 1, (int)floorf((gy2 + EXPAND) * BINW_INV));
    for (int by = by0; by <= by1; by++)
        for (int bx = bx0; bx <= bx1; bx++) {
            int bin = img * NBIN + by * BINS + bx;
            int slot = atomicAdd(&g_bincnt[bin], 1);
            g_bingt[(size_t)bin * GTCAP + slot] = (unsigned char)j;
        }
}

// R8-identical focal
__device__ __forceinline__ float focal_term(float l, bool pos) {
    float t = pos ? 1.0f : 0.0f;
    float bce = fmaxf(l, 0.0f) - l * t + __logf(1.0f + __expf(-fabsf(l)));
    float pp = __fdividef(1.0f, 1.0f + __expf(-l));
    float p_t = pos ? pp : 1.0f - pp;
    float a_t = pos ? ALPHA_C : 1.0f - ALPHA_C;
    float om = 1.0f - p_t;
    return a_t * om * om * bce;
}

__device__ __forceinline__ float giou_term(float x1, float y1, float x2, float y2,
                                           float gx1, float gy1, float gx2, float gy2) {
    float ix1 = fmaxf(x1, gx1), iy1 = fmaxf(y1, gy1);
    float ix2 = fminf(x2, gx2), iy2 = fminf(y2, gy2);
    float inter = fmaxf(ix2 - ix1, 0.0f) * fmaxf(iy2 - iy1, 0.0f);
    float ap = (x2 - x1) * (y2 - y1);
    float ag = (gx2 - gx1) * (gy2 - gy1);
    float uni = ap + ag - inter;
    float iou = __fdividef(inter, fmaxf(uni, EPSI));
    float ex1 = fminf(x1, gx1), ey1 = fminf(y1, gy1);
    float ex2 = fmaxf(x2, gx2), ey2 = fmaxf(y2, gy2);
    float enc = (ex2 - ex1) * (ey2 - ey1);
    float giou = iou - __fdividef(enc - uni, fmaxf(enc, EPSI));
    return 1.0f - giou;
}

// ---------------- KB: main pred-stationary pass (R8-identical) ----------------
#define KB_THREADS 256
#define KB_T 8

__global__ __launch_bounds__(KB_THREADS)
void kb_main(const float* __restrict__ pred, const float* __restrict__ gt) {
    __shared__ float sgx1[MM], sgy1[MM], sgx2[MM], sgy2[MM], sga[MM];
    __shared__ unsigned long long shcol[MM];
    __shared__ float red[4][8];

    const int img = blockIdx.y;
    const int tid = threadIdx.x;

    if (tid < MM) {
        const float* g = gt + ((size_t)img * MM + tid) * 4;
        float x1 = g[0], y1 = g[1], x2 = g[2], y2 = g[3];
        sgx1[tid] = x1; sgy1[tid] = y1; sgx2[tid] = x2; sgy2[tid] = y2;
        sga[tid] = (x2 - x1) * (y2 - y1);
        shcol[tid] = 0ull;
    }
    __syncthreads();

    const int base = blockIdx.x * (KB_THREADS * KB_T);
    float s_cls = 0.0f, s_reg = 0.0f, c_v = 0.0f, c_p = 0.0f;

    for (int k = 0; k < KB_T; k++) {
        int idx = base + k * KB_THREADS + tid;
        const float* p = pred + ((size_t)img * NN + idx) * 5;
        float cx = p[0], cy = p[1], w = p[2], h = p[3], l = p[4];
        float x1 = cx - 0.5f * w, y1 = cy - 0.5f * h;
        float x2 = cx + 0.5f * w, y2 = cy + 0.5f * h;
        float pa = (x2 - x1) * (y2 - y1);

        int bx = min(BINS - 1, (int)(cx * BINW_INV));
        int by = min(BINS - 1, (int)(cy * BINW_INV));
        int bin = img * NBIN + by * BINS + bx;
        int cnt = g_bincnt[bin];
        const unsigned char* lst = g_bingt + (size_t)bin * GTCAP;

        float bv = 0.0f; int bj = 0;
        for (int t0 = 0; t0 < cnt; t0 += 8) {
            unsigned long long pk = *(const unsigned long long*)(lst + t0);
            int lim = min(8, cnt - t0);
            for (int tt = 0; tt < lim; tt++) {
                int j = (int)((pk >> (8 * tt)) & 0xFFull);
                float ix1 = fmaxf(x1, sgx1[j]), iy1 = fmaxf(y1, sgy1[j]);
                float ix2 = fminf(x2, sgx2[j]), iy2 = fminf(y2, sgy2[j]);
                float inter = fmaxf(ix2 - ix1, 0.0f) * fmaxf(iy2 - iy1, 0.0f);
                float uni = pa + sga[j] - inter;
                float iou = __fdividef(inter, fmaxf(uni, EPSI));
                if (iou > bv || (iou == bv && j < bj)) { bv = iou; bj = j; }
                if (iou > SCAT_THR) {
                    unsigned long long key =
                        ((unsigned long long)__float_as_uint(iou) << 32) |
                        (0xFFFFFFFFu - (unsigned int)idx);
                    atomicMax(&shcol[j], key);
                }
            }
        }

        bool pos = bv > POS_THR;
        bool neg = bv < NEG_THR;
        bool valid = pos || neg;
        float fl = focal_term(l, pos);
        float gterm = giou_term(x1, y1, x2, y2,
                                sgx1[bj], sgy1[bj], sgx2[bj], sgy2[bj]);
        s_cls += valid ? fl : 0.0f;
        s_reg += pos ? gterm : 0.0f;
        c_v   += valid ? 1.0f : 0.0f;
        c_p   += pos ? 1.0f : 0.0f;
    }

#pragma unroll
    for (int off = 16; off; off >>= 1) {
        s_cls += __shfl_down_sync(0xFFFFFFFFu, s_cls, off);
        s_reg += __shfl_down_sync(0xFFFFFFFFu, s_reg, off);
        c_v   += __shfl_down_sync(0xFFFFFFFFu, c_v, off);
        c_p   += __shfl_down_sync(0xFFFFFFFFu, c_p, off);
    }
    int wid = tid >> 5, lid = tid & 31;
    if (lid == 0) { red[0][wid] = s_cls; red[1][wid] = s_reg; red[2][wid] = c_v; red[3][wid] = c_p; }
    __syncthreads();
    if (tid < MM) {
        unsigned long long v = shcol[tid];
        if (v) atomicMax(&g_colmax[img * MM + tid], v);
    }
    if (tid == 0) {
        float a = 0, b = 0, c = 0, d = 0;
#pragma unroll
        for (int i = 0; i < 8; i++) { a += red[0][i]; b += red[1][i]; c += red[2][i]; d += red[3][i]; }
        atomicAdd(&g_acc[img][0], a);
        atomicAdd(&g_acc[img][1], b);
        atomicAdd(&g_acc[img][2], c);
        atomicAdd(&g_acc[img][3], d);
    }
}

// ---------------- K2: scatter fixup (R8-identical) ----------------
__global__ void k2_fixup(const float* __restrict__ pred, const float* __restrict__ gt) {
    __shared__ int s_pred[MM];
    __shared__ int s_gate[MM];

    int img = blockIdx.x;
    int j = threadIdx.x;   // 64 threads

    unsigned long long v = g_colmax[img * MM + j];
    float val = __uint_as_float((unsigned int)(v >> 32));
    unsigned int pidx = 0xFFFFFFFFu - (unsigned int)(v & 0xFFFFFFFFull);
    int gate = (val > SCAT_THR && pidx < NN) ? 1 : 0;
    s_pred[j] = (int)pidx;
    s_gate[j] = gate;
    __syncthreads();

    bool mine = gate;
    if (gate) {
        for (int q = 0; q < j; q++)
            if (s_gate[q] && s_pred[q] == (int)pidx) { mine = false; break; }
    }
    if (!mine) return;

    int i = (int)pidx;
    const float* p = pred + ((size_t)img * NN + i) * 5;
    float cx = p[0], cy = p[1], w = p[2], h = p[3], l = p[4];
    float x1 = cx - 0.5f * w, y1 = cy - 0.5f * h;
    float x2 = cx + 0.5f * w, y2 = cy + 0.5f * h;
    float pa = (x2 - x1) * (y2 - y1);

    int bx = min(BINS - 1, (int)(cx * BINW_INV));
    int by = min(BINS - 1, (int)(cy * BINW_INV));
    int bin = img * NBIN + by * BINS + bx;
    int cnt = g_bincnt[bin];
    const unsigned char* lst = g_bingt + (size_t)bin * GTCAP;
    const float* gbase = gt + (size_t)img * MM * 4;
    float bv = 0.0f; int bj = 0;
    for (int t0 = 0; t0 < cnt; t0 += 8) {
        unsigned long long pk = *(const unsigned long long*)(lst + t0);
        int lim = min(8, cnt - t0);
        for (int tt = 0; tt < lim; tt++) {
            int jj = (int)((pk >> (8 * tt)) & 0xFFull);
            const float* g = gbase + jj * 4;
            float gx1 = g[0], gy1 = g[1], gx2 = g[2], gy2 = g[3];
            float ix1 = fmaxf(x1, gx1), iy1 = fmaxf(y1, gy1);
            float ix2 = fminf(x2, gx2), iy2 = fminf(y2, gy2);
            float inter = fmaxf(ix2 - ix1, 0.0f) * fmaxf(iy2 - iy1, 0.0f);
            float uni = pa + (gx2 - gx1) * (gy2 - gy1) - inter;
            float iou = __fdividef(inter, fmaxf(uni, EPSI));
            if (iou > bv || (iou == bv && jj < bj)) { bv = iou; bj = jj; }
        }
    }

    bool pos0 = bv > POS_THR;
    if (pos0) return;

    bool neg = bv < NEG_THR;
    float fl1 = focal_term(l, true);
    float fl0 = focal_term(l, false);
    const float* gm = gbase + bj * 4;
    float gterm = giou_term(x1, y1, x2, y2, gm[0], gm[1], gm[2], gm[3]);

    float d_cls = fl1 - (neg ? fl0 : 0.0f);
    float d_v   = neg ? 0.0f : 1.0f;
    atomicAdd(&g_acc[img][0], d_cls);
    atomicAdd(&g_acc[img][1], gterm);
    atomicAdd(&g_acc[img][2], d_v);
    atomicAdd(&g_acc[img][3], 1.0f);
}

// ---------------- K4: final scalar (R8-identical) ----------------
__global__ void k4_final(float* __restrict__ out) {
    int tid = threadIdx.x;  // 32 threads = BB images
    float sc = g_acc[tid][0], sr = g_acc[tid][1];
    float vc = g_acc[tid][2], pc = g_acc[tid][3];
    float cls = (vc > 0.0f) ? sc / fmaxf(vc, 1.0f) : 0.0f;
    float reg = (pc > 0.0f) ? sr / fmaxf(pc, 1.0f) : 0.0f;
    float np = pc;
#pragma unroll
    for (int off = 16; off; off >>= 1) {
        cls += __shfl_down_sync(0xFFFFFFFFu, cls, off);
        reg += __shfl_down_sync(0xFFFFFFFFu, reg, off);
        np  += __shfl_down_sync(0xFFFFFFFFu, np, off);
    }
    if (tid == 0) {
        float num_pos = fmaxf(np, 1.0f);
        out[0] = cls / (float)BB + BBOX_W * (reg / num_pos * (float)BB);
    }
}

extern "C" void kernel_launch(void* const* d_in, const int* in_sizes, int n_in,
                              void* d_out, int out_size) {
    const float* pred = (const float*)d_in[0];  // [B, N, 5]
    const float* gt   = (const float*)d_in[1];  // [B, M, 4]
    float* out = (float*)d_out;

    k0_init<<<BB * NBIN / 256, 256>>>();
    ka_bins<<<BB, MM>>>(gt);
    dim3 gb(NN / (KB_THREADS * KB_T), BB);
    kb_main<<<gb, KB_THREADS>>>(pred, gt);
    k2_fixup<<<BB, MM>>>(pred, gt);
    k4_final<<<1, 32>>>(out);
}

// round 15
// speedup vs baseline: 1.6159x; 1.2090x over previous
#include <cuda_runtime.h>

#define BB 32
#define NN 65536
#define MM 64

#define BINS 16
#define NBIN (BINS * BINS)
#define BINW_INV 0.025f      // 1/40px
#define EXPAND 36.0f         // max pred half-extent (w < 72)
#define GTCAP 64             // list cap = MM, cannot overflow

static __device__ unsigned long long g_colmax[BB * MM];
static __device__ float g_acc[BB][4];                 // cls_sum, reg_sum, vcnt, pcnt
static __device__ int g_bincnt[BB * NBIN];
static __device__ unsigned char g_bingt[BB * NBIN * GTCAP];

#define POS_THR 0.5f
#define NEG_THR 0.4f
#define SCAT_THR 0.1f
#define ALPHA_C 0.25f
#define BBOX_W 2.0f
#define EPSI 1e-6f

// ---------------- K0: init scratch (R8-identical) ----------------
__global__ void k0_init() {
    int i = blockIdx.x * blockDim.x + threadIdx.x;   // 8192 threads
    g_bincnt[i] = 0;
    if (i < BB * MM) g_colmax[i] = 0ull;
    if (i < BB * 4) ((float*)g_acc)[i] = 0.0f;
}

// ---------------- KA: per-bin gt lists (R8-identical) ----------------
__global__ void ka_bins(const float* __restrict__ gt) {
    int img = blockIdx.x;
    int j = threadIdx.x;  // 64 threads = gts
    const float* g = gt + ((size_t)img * MM + j) * 4;
    float gx1 = g[0], gy1 = g[1], gx2 = g[2], gy2 = g[3];
    int bx0 = max(0, (int)floorf((gx1 - EXPAND) * BINW_INV));
    int bx1 = min(BINS - 1, (int)floorf((gx2 + EXPAND) * BINW_INV));
    int by0 = max(0, (int)floorf((gy1 - EXPAND) * BINW_INV));
    int by1 = min(BINS - 1, (int)floorf((gy2 + EXPAND) * BINW_INV));
    for (int by = by0; by <= by1; by++)
        for (int bx = bx0; bx <= bx1; bx++) {
            int bin = img * NBIN + by * BINS + bx;
            int slot = atomicAdd(&g_bincnt[bin], 1);
            g_bingt[(size_t)bin * GTCAP + slot] = (unsigned char)j;
        }
}

// R8-identical focal
__device__ __forceinline__ float focal_term(float l, bool pos) {
    float t = pos ? 1.0f : 0.0f;
    float bce = fmaxf(l, 0.0f) - l * t + __logf(1.0f + __expf(-fabsf(l)));
    float pp = __fdividef(1.0f, 1.0f + __expf(-l));
    float p_t = pos ? pp : 1.0f - pp;
    float a_t = pos ? ALPHA_C : 1.0f - ALPHA_C;
    float om = 1.0f - p_t;
    return a_t * om * om * bce;
}

__device__ __forceinline__ float giou_term(float x1, float y1, float x2, float y2,
                                           float gx1, float gy1, float gx2, float gy2) {
    float ix1 = fmaxf(x1, gx1), iy1 = fmaxf(y1, gy1);
    float ix2 = fminf(x2, gx2), iy2 = fminf(y2, gy2);
    float inter = fmaxf(ix2 - ix1, 0.0f) * fmaxf(iy2 - iy1, 0.0f);
    float ap = (x2 - x1) * (y2 - y1);
    float ag = (gx2 - gx1) * (gy2 - gy1);
    float uni = ap + ag - inter;
    float iou = __fdividef(inter, fmaxf(uni, EPSI));
    float ex1 = fminf(x1, gx1), ey1 = fminf(y1, gy1);
    float ex2 = fmaxf(x2, gx2), ey2 = fmaxf(y2, gy2);
    float enc = (ex2 - ex1) * (ey2 - ey1);
    float giou = iou - __fdividef(enc - uni, fmaxf(enc, EPSI));
    return 1.0f - giou;
}

// ---------------- KB: main pass (R8 + whole bin table staged in smem) ----------------
#define KB_THREADS 256
#define KB_T 8

__global__ __launch_bounds__(KB_THREADS)
void kb_main(const float* __restrict__ pred, const float* __restrict__ gt) {
    __shared__ float sgx1[MM], sgy1[MM], sgx2[MM], sgy2[MM], sga[MM];
    __shared__ unsigned long long shcol[MM];
    __shared__ float red[4][8];
    __shared__ unsigned char slist[NBIN * GTCAP];   // 16KB: this image's full bin table
    __shared__ int scnt[NBIN];                      // 1KB

    const int img = blockIdx.y;
    const int tid = threadIdx.x;

    if (tid < MM) {
        const float* g = gt + ((size_t)img * MM + tid) * 4;
        float x1 = g[0], y1 = g[1], x2 = g[2], y2 = g[3];
        sgx1[tid] = x1; sgy1[tid] = y1; sgx2[tid] = x2; sgy2[tid] = y2;
        sga[tid] = (x2 - x1) * (y2 - y1);
        shcol[tid] = 0ull;
    }
    // cooperative coalesced copy of the bin table (u32 granularity)
    {
        const unsigned int* src = (const unsigned int*)(g_bingt + (size_t)img * NBIN * GTCAP);
        unsigned int* dst = (unsigned int*)slist;
#pragma unroll
        for (int i = 0; i < (NBIN * GTCAP / 4) / KB_THREADS; i++)
            dst[tid + i * KB_THREADS] = src[tid + i * KB_THREADS];
        scnt[tid] = g_bincnt[img * NBIN + tid];   // KB_THREADS == NBIN
    }
    __syncthreads();

    const int base = blockIdx.x * (KB_THREADS * KB_T);
    float s_cls = 0.0f, s_reg = 0.0f, c_v = 0.0f, c_p = 0.0f;

    for (int k = 0; k < KB_T; k++) {
        int idx = base + k * KB_THREADS + tid;
        const float* p = pred + ((size_t)img * NN + idx) * 5;
        float cx = p[0], cy = p[1], w = p[2], h = p[3], l = p[4];
        float x1 = cx - 0.5f * w, y1 = cy - 0.5f * h;
        float x2 = cx + 0.5f * w, y2 = cy + 0.5f * h;
        float pa = (x2 - x1) * (y2 - y1);

        int bx = min(BINS - 1, (int)(cx * BINW_INV));
        int by = min(BINS - 1, (int)(cy * BINW_INV));
        int bin = by * BINS + bx;
        int cnt = scnt[bin];
        const unsigned char* lst = slist + bin * GTCAP;

        float bv = 0.0f; int bj = 0;
        for (int t0 = 0; t0 < cnt; t0 += 8) {
            unsigned long long pk = *(const unsigned long long*)(lst + t0);
            int lim = min(8, cnt - t0);
            for (int tt = 0; tt < lim; tt++) {
                int j = (int)((pk >> (8 * tt)) & 0xFFull);
                float ix1 = fmaxf(x1, sgx1[j]), iy1 = fmaxf(y1, sgy1[j]);
                float ix2 = fminf(x2, sgx2[j]), iy2 = fminf(y2, sgy2[j]);
                float inter = fmaxf(ix2 - ix1, 0.0f) * fmaxf(iy2 - iy1, 0.0f);
                float uni = pa + sga[j] - inter;
                float iou = __fdividef(inter, fmaxf(uni, EPSI));
                if (iou > bv || (iou == bv && j < bj)) { bv = iou; bj = j; }
                if (iou > SCAT_THR) {
                    unsigned long long key =
                        ((unsigned long long)__float_as_uint(iou) << 32) |
                        (0xFFFFFFFFu - (unsigned int)idx);
                    atomicMax(&shcol[j], key);
                }
            }
        }

        bool pos = bv > POS_THR;
        bool neg = bv < NEG_THR;
        bool valid = pos || neg;
        float fl = focal_term(l, pos);
        float gterm = giou_term(x1, y1, x2, y2,
                                sgx1[bj], sgy1[bj], sgx2[bj], sgy2[bj]);
        s_cls += valid ? fl : 0.0f;
        s_reg += pos ? gterm : 0.0f;
        c_v   += valid ? 1.0f : 0.0f;
        c_p   += pos ? 1.0f : 0.0f;
    }

#pragma unroll
    for (int off = 16; off; off >>= 1) {
        s_cls += __shfl_down_sync(0xFFFFFFFFu, s_cls, off);
        s_reg += __shfl_down_sync(0xFFFFFFFFu, s_reg, off);
        c_v   += __shfl_down_sync(0xFFFFFFFFu, c_v, off);
        c_p   += __shfl_down_sync(0xFFFFFFFFu, c_p, off);
    }
    int wid = tid >> 5, lid = tid & 31;
    if (lid == 0) { red[0][wid] = s_cls; red[1][wid] = s_reg; red[2][wid] = c_v; red[3][wid] = c_p; }
    __syncthreads();
    if (tid < MM) {
        unsigned long long v = shcol[tid];
        if (v) atomicMax(&g_colmax[img * MM + tid], v);
    }
    if (tid == 0) {
        float a = 0, b = 0, c = 0, d = 0;
#pragma unroll
        for (int i = 0; i < 8; i++) { a += red[0][i]; b += red[1][i]; c += red[2][i]; d += red[3][i]; }
        atomicAdd(&g_acc[img][0], a);
        atomicAdd(&g_acc[img][1], b);
        atomicAdd(&g_acc[img][2], c);
        atomicAdd(&g_acc[img][3], d);
    }
}

// ---------------- K2: scatter fixup (R8-identical) ----------------
__global__ void k2_fixup(const float* __restrict__ pred, const float* __restrict__ gt) {
    __shared__ int s_pred[MM];
    __shared__ int s_gate[MM];

    int img = blockIdx.x;
    int j = threadIdx.x;   // 64 threads

    unsigned long long v = g_colmax[img * MM + j];
    float val = __uint_as_float((unsigned int)(v >> 32));
    unsigned int pidx = 0xFFFFFFFFu - (unsigned int)(v & 0xFFFFFFFFull);
    int gate = (val > SCAT_THR && pidx < NN) ? 1 : 0;
    s_pred[j] = (int)pidx;
    s_gate[j] = gate;
    __syncthreads();

    bool mine = gate;
    if (gate) {
        for (int q = 0; q < j; q++)
            if (s_gate[q] && s_pred[q] == (int)pidx) { mine = false; break; }
    }
    if (!mine) return;

    int i = (int)pidx;
    const float* p = pred + ((size_t)img * NN + i) * 5;
    float cx = p[0], cy = p[1], w = p[2], h = p[3], l = p[4];
    float x1 = cx - 0.5f * w, y1 = cy - 0.5f * h;
    float x2 = cx + 0.5f * w, y2 = cy + 0.5f * h;
    float pa = (x2 - x1) * (y2 - y1);

    int bx = min(BINS - 1, (int)(cx * BINW_INV));
    int by = min(BINS - 1, (int)(cy * BINW_INV));
    int bin = img * NBIN + by * BINS + bx;
    int cnt = g_bincnt[bin];
    const unsigned char* lst = g_bingt + (size_t)bin * GTCAP;
    const float* gbase = gt + (size_t)img * MM * 4;
    float bv = 0.0f; int bj = 0;
    for (int t0 = 0; t0 < cnt; t0 += 8) {
        unsigned long long pk = *(const unsigned long long*)(lst + t0);
        int lim = min(8, cnt - t0);
        for (int tt = 0; tt < lim; tt++) {
            int jj = (int)((pk >> (8 * tt)) & 0xFFull);
            const float* g = gbase + jj * 4;
            float gx1 = g[0], gy1 = g[1], gx2 = g[2], gy2 = g[3];
            float ix1 = fmaxf(x1, gx1), iy1 = fmaxf(y1, gy1);
            float ix2 = fminf(x2, gx2), iy2 = fminf(y2, gy2);
            float inter = fmaxf(ix2 - ix1, 0.0f) * fmaxf(iy2 - iy1, 0.0f);
            float uni = pa + (gx2 - gx1) * (gy2 - gy1) - inter;
            float iou = __fdividef(inter, fmaxf(uni, EPSI));
            if (iou > bv || (iou == bv && jj < bj)) { bv = iou; bj = jj; }
        }
    }

    bool pos0 = bv > POS_THR;
    if (pos0) return;

    bool neg = bv < NEG_THR;
    float fl1 = focal_term(l, true);
    float fl0 = focal_term(l, false);
    const float* gm = gbase + bj * 4;
    float gterm = giou_term(x1, y1, x2, y2, gm[0], gm[1], gm[2], gm[3]);

    float d_cls = fl1 - (neg ? fl0 : 0.0f);
    float d_v   = neg ? 0.0f : 1.0f;
    atomicAdd(&g_acc[img][0], d_cls);
    atomicAdd(&g_acc[img][1], gterm);
    atomicAdd(&g_acc[img][2], d_v);
    atomicAdd(&g_acc[img][3], 1.0f);
}

// ---------------- K4: final scalar (R8-identical) ----------------
__global__ void k4_final(float* __restrict__ out) {
    int tid = threadIdx.x;  // 32 threads = BB images
    float sc = g_acc[tid][0], sr = g_acc[tid][1];
    float vc = g_acc[tid][2], pc = g_acc[tid][3];
    float cls = (vc > 0.0f) ? sc / fmaxf(vc, 1.0f) : 0.0f;
    float reg = (pc > 0.0f) ? sr / fmaxf(pc, 1.0f) : 0.0f;
    float np = pc;
#pragma unroll
    for (int off = 16; off; off >>= 1) {
        cls += __shfl_down_sync(0xFFFFFFFFu, cls, off);
        reg += __shfl_down_sync(0xFFFFFFFFu, reg, off);
        np  += __shfl_down_sync(0xFFFFFFFFu, np, off);
    }
    if (tid == 0) {
        float num_pos = fmaxf(np, 1.0f);
        out[0] = cls / (float)BB + BBOX_W * (reg / num_pos * (float)BB);
    }
}

extern "C" void kernel_launch(void* const* d_in, const int* in_sizes, int n_in,
                              void* d_out, int out_size) {
    const float* pred = (const float*)d_in[0];  // [B, N, 5]
    const float* gt   = (const float*)d_in[1];  // [B, M, 4]
    float* out = (float*)d_out;

    k0_init<<<BB * NBIN / 256, 256>>>();
    ka_bins<<<BB, MM>>>(gt);
    dim3 gb(NN / (KB_THREADS * KB_T), BB);
    kb_main<<<gb, KB_THREADS>>>(pred, gt);
    k2_fixup<<<BB, MM>>>(pred, gt);
    k4_final<<<1, 32>>>(out);
}

// round 16
// speedup vs baseline: 1.7141x; 1.0608x over previous
#include <cuda_runtime.h>

#define BB 32
#define NN 65536
#define MM 64

#define BINS 16
#define NBIN (BINS * BINS)
#define BINW_INV 0.025f      // 1/40px
#define EXPAND 36.0f         // max pred half-extent (w < 72)
#define GTCAP 64             // list cap = MM, cannot overflow

static __device__ unsigned long long g_colmax[BB * MM];
static __device__ float g_acc[BB][4];                 // cls_sum, reg_sum, vcnt, pcnt
static __device__ int g_bincnt[BB * NBIN];
static __device__ unsigned char g_bingt[BB * NBIN * GTCAP];

#define POS_THR 0.5f
#define NEG_THR 0.4f
#define SCAT_THR 0.1f
#define ALPHA_C 0.25f
#define BBOX_W 2.0f
#define EPSI 1e-6f

// ---------------- KIB: fused init + per-bin gt lists (R9 version, proven) ----------------
__global__ __launch_bounds__(NBIN)
void kib_init_bins(const float* __restrict__ gt) {
    int img = blockIdx.x;
    int tid = threadIdx.x;   // 256

    g_bincnt[img * NBIN + tid] = 0;
    if (tid < MM) g_colmax[img * MM + tid] = 0ull;
    if (tid < 4) g_acc[img][tid] = 0.0f;
    __syncthreads();

    if (tid < MM) {
        const float* g = gt + ((size_t)img * MM + tid) * 4;
        float gx1 = g[0], gy1 = g[1], gx2 = g[2], gy2 = g[3];
        int bx0 = max(0, (int)floorf((gx1 - EXPAND) * BINW_INV));
        int bx1 = min(BINS - 1, (int)floorf((gx2 + EXPAND) * BINW_INV));
        int by0 = max(0, (int)floorf((gy1 - EXPAND) * BINW_INV));
        int by1 = min(BINS - 1, (int)floorf((gy2 + EXPAND) * BINW_INV));
        for (int by = by0; by <= by1; by++)
            for (int bx = bx0; bx <= bx1; bx++) {
                int bin = img * NBIN + by * BINS + bx;
                int slot = atomicAdd(&g_bincnt[bin], 1);
                g_bingt[(size_t)bin * GTCAP + slot] = (unsigned char)tid;
            }
    }
}

// one-expf focal (R9 version; sigmoid identity is exact)
__device__ __forceinline__ float focal_term(float l, bool pos) {
    float t = pos ? 1.0f : 0.0f;
    float e = __expf(-fabsf(l));
    float bce = fmaxf(l, 0.0f) - l * t + __logf(1.0f + e);
    float inv = __fdividef(1.0f, 1.0f + e);
    float pp = (l >= 0.0f) ? inv : e * inv;      // sigmoid(l)
    float p_t = pos ? pp : 1.0f - pp;
    float a_t = pos ? ALPHA_C : 1.0f - ALPHA_C;
    float om = 1.0f - p_t;
    return a_t * om * om * bce;
}

__device__ __forceinline__ float giou_term(float x1, float y1, float x2, float y2,
                                           float gx1, float gy1, float gx2, float gy2) {
    float ix1 = fmaxf(x1, gx1), iy1 = fmaxf(y1, gy1);
    float ix2 = fminf(x2, gx2), iy2 = fminf(y2, gy2);
    float inter = fmaxf(ix2 - ix1, 0.0f) * fmaxf(iy2 - iy1, 0.0f);
    float ap = (x2 - x1) * (y2 - y1);
    float ag = (gx2 - gx1) * (gy2 - gy1);
    float uni = ap + ag - inter;
    float iou = __fdividef(inter, fmaxf(uni, EPSI));
    float ex1 = fminf(x1, gx1), ey1 = fminf(y1, gy1);
    float ex2 = fmaxf(x2, gx2), ey2 = fmaxf(y2, gy2);
    float enc = (ex2 - ex1) * (ey2 - ey1);
    float giou = iou - __fdividef(enc - uni, fmaxf(enc, EPSI));
    return 1.0f - giou;
}

// ---------------- KB: main pass (R8 internals, R9 epilogue) ----------------
#define KB_THREADS 256
#define KB_T 8

__global__ __launch_bounds__(KB_THREADS)
void kb_main(const float* __restrict__ pred, const float* __restrict__ gt) {
    __shared__ float sgx1[MM], sgy1[MM], sgx2[MM], sgy2[MM], sga[MM];
    __shared__ unsigned long long shcol[MM];
    __shared__ float red[4][8];

    const int img = blockIdx.y;
    const int tid = threadIdx.x;

    if (tid < MM) {
        const float* g = gt + ((size_t)img * MM + tid) * 4;
        float x1 = g[0], y1 = g[1], x2 = g[2], y2 = g[3];
        sgx1[tid] = x1; sgy1[tid] = y1; sgx2[tid] = x2; sgy2[tid] = y2;
        sga[tid] = (x2 - x1) * (y2 - y1);
        shcol[tid] = 0ull;
    }
    __syncthreads();

    const int base = blockIdx.x * (KB_THREADS * KB_T);
    float s_cls = 0.0f, s_reg = 0.0f, c_v = 0.0f, c_p = 0.0f;

    for (int k = 0; k < KB_T; k++) {
        int idx = base + k * KB_THREADS + tid;
        const float* p = pred + ((size_t)img * NN + idx) * 5;
        float cx = p[0], cy = p[1], w = p[2], h = p[3], l = p[4];
        float x1 = cx - 0.5f * w, y1 = cy - 0.5f * h;
        float x2 = cx + 0.5f * w, y2 = cy + 0.5f * h;
        float pa = (x2 - x1) * (y2 - y1);

        int bx = min(BINS - 1, (int)(cx * BINW_INV));
        int by = min(BINS - 1, (int)(cy * BINW_INV));
        int bin = img * NBIN + by * BINS + bx;
        int cnt = g_bincnt[bin];
        const unsigned char* lst = g_bingt + (size_t)bin * GTCAP;

        float bv = 0.0f; int bj = 0;
        for (int t0 = 0; t0 < cnt; t0 += 8) {
            unsigned long long pk = *(const unsigned long long*)(lst + t0);
            int lim = min(8, cnt - t0);
            for (int tt = 0; tt < lim; tt++) {
                int j = (int)((pk >> (8 * tt)) & 0xFFull);
                float ix1 = fmaxf(x1, sgx1[j]), iy1 = fmaxf(y1, sgy1[j]);
                float ix2 = fminf(x2, sgx2[j]), iy2 = fminf(y2, sgy2[j]);
                float inter = fmaxf(ix2 - ix1, 0.0f) * fmaxf(iy2 - iy1, 0.0f);
                float uni = pa + sga[j] - inter;
                float iou = __fdividef(inter, fmaxf(uni, EPSI));
                if (iou > bv || (iou == bv && j < bj)) { bv = iou; bj = j; }
                if (iou > SCAT_THR) {
                    unsigned long long key =
                        ((unsigned long long)__float_as_uint(iou) << 32) |
                        (0xFFFFFFFFu - (unsigned int)idx);
                    atomicMax(&shcol[j], key);
                }
            }
        }

        bool pos = bv > POS_THR;
        bool neg = bv < NEG_THR;
        bool valid = pos || neg;
        float fl = focal_term(l, pos);
        s_cls += valid ? fl : 0.0f;
        c_v   += valid ? 1.0f : 0.0f;
        if (pos) {   // warp skips giou when no lane is pos (R9 epilogue)
            float gterm = giou_term(x1, y1, x2, y2,
                                    sgx1[bj], sgy1[bj], sgx2[bj], sgy2[bj]);
            s_reg += gterm;
            c_p   += 1.0f;
        }
    }

#pragma unroll
    for (int off = 16; off; off >>= 1) {
        s_cls += __shfl_down_sync(0xFFFFFFFFu, s_cls, off);
        s_reg += __shfl_down_sync(0xFFFFFFFFu, s_reg, off);
        c_v   += __shfl_down_sync(0xFFFFFFFFu, c_v, off);
        c_p   += __shfl_down_sync(0xFFFFFFFFu, c_p, off);
    }
    int wid = tid >> 5, lid = tid & 31;
    if (lid == 0) { red[0][wid] = s_cls; red[1][wid] = s_reg; red[2][wid] = c_v; red[3][wid] = c_p; }
    __syncthreads();
    if (tid < MM) {
        unsigned long long v = shcol[tid];
        if (v) atomicMax(&g_colmax[img * MM + tid], v);
    }
    if (tid == 0) {
        float a = 0, b = 0, c = 0, d = 0;
#pragma unroll
        for (int i = 0; i < 8; i++) { a += red[0][i]; b += red[1][i]; c += red[2][i]; d += red[3][i]; }
        atomicAdd(&g_acc[img][0], a);
        atomicAdd(&g_acc[img][1], b);
        atomicAdd(&g_acc[img][2], c);
        atomicAdd(&g_acc[img][3], d);
    }
}

// ---------------- K2: scatter fixup (R8-identical) ----------------
__global__ void k2_fixup(const float* __restrict__ pred, const float* __restrict__ gt) {
    __shared__ int s_pred[MM];
    __shared__ int s_gate[MM];

    int img = blockIdx.x;
    int j = threadIdx.x;   // 64 threads

    unsigned long long v = g_colmax[img * MM + j];
    float val = __uint_as_float((unsigned int)(v >> 32));
    unsigned int pidx = 0xFFFFFFFFu - (unsigned int)(v & 0xFFFFFFFFull);
    int gate = (val > SCAT_THR && pidx < NN) ? 1 : 0;
    s_pred[j] = (int)pidx;
    s_gate[j] = gate;
    __syncthreads();

    bool mine = gate;
    if (gate) {
        for (int q = 0; q < j; q++)
            if (s_gate[q] && s_pred[q] == (int)pidx) { mine = false; break; }
    }
    if (!mine) return;

    int i = (int)pidx;
    const float* p = pred + ((size_t)img * NN + i) * 5;
    float cx = p[0], cy = p[1], w = p[2], h = p[3], l = p[4];
    float x1 = cx - 0.5f * w, y1 = cy - 0.5f * h;
    float x2 = cx + 0.5f * w, y2 = cy + 0.5f * h;
    float pa = (x2 - x1) * (y2 - y1);

    int bx = min(BINS - 1, (int)(cx * BINW_INV));
    int by = min(BINS - 1, (int)(cy * BINW_INV));
    int bin = img * NBIN + by * BINS + bx;
    int cnt = g_bincnt[bin];
    const unsigned char* lst = g_bingt + (size_t)bin * GTCAP;
    const float* gbase = gt + (size_t)img * MM * 4;
    float bv = 0.0f; int bj = 0;
    for (int t0 = 0; t0 < cnt; t0 += 8) {
        unsigned long long pk = *(const unsigned long long*)(lst + t0);
        int lim = min(8, cnt - t0);
        for (int tt = 0; tt < lim; tt++) {
            int jj = (int)((pk >> (8 * tt)) & 0xFFull);
            const float* g = gbase + jj * 4;
            float gx1 = g[0], gy1 = g[1], gx2 = g[2], gy2 = g[3];
            float ix1 = fmaxf(x1, gx1), iy1 = fmaxf(y1, gy1);
            float ix2 = fminf(x2, gx2), iy2 = fminf(y2, gy2);
            float inter = fmaxf(ix2 - ix1, 0.0f) * fmaxf(iy2 - iy1, 0.0f);
            float uni = pa + (gx2 - gx1) * (gy2 - gy1) - inter;
            float iou = __fdividef(inter, fmaxf(uni, EPSI));
            if (iou > bv || (iou == bv && jj < bj)) { bv = iou; bj = jj; }
        }
    }

    bool pos0 = bv > POS_THR;
    if (pos0) return;

    bool neg = bv < NEG_THR;
    float fl1 = focal_term(l, true);
    float fl0 = focal_term(l, false);
    const float* gm = gbase + bj * 4;
    float gterm = giou_term(x1, y1, x2, y2, gm[0], gm[1], gm[2], gm[3]);

    float d_cls = fl1 - (neg ? fl0 : 0.0f);
    float d_v   = neg ? 0.0f : 1.0f;
    atomicAdd(&g_acc[img][0], d_cls);
    atomicAdd(&g_acc[img][1], gterm);
    atomicAdd(&g_acc[img][2], d_v);
    atomicAdd(&g_acc[img][3], 1.0f);
}

// ---------------- K4: final scalar (R8-identical) ----------------
__global__ void k4_final(float* __restrict__ out) {
    int tid = threadIdx.x;  // 32 threads = BB images
    float sc = g_acc[tid][0], sr = g_acc[tid][1];
    float vc = g_acc[tid][2], pc = g_acc[tid][3];
    float cls = (vc > 0.0f) ? sc / fmaxf(vc, 1.0f) : 0.0f;
    float reg = (pc > 0.0f) ? sr / fmaxf(pc, 1.0f) : 0.0f;
    float np = pc;
#pragma unroll
    for (int off = 16; off; off >>= 1) {
        cls += __shfl_down_sync(0xFFFFFFFFu, cls, off);
        reg += __shfl_down_sync(0xFFFFFFFFu, reg, off);
        np  += __shfl_down_sync(0xFFFFFFFFu, np, off);
    }
    if (tid == 0) {
        float num_pos = fmaxf(np, 1.0f);
        out[0] = cls / (float)BB + BBOX_W * (reg / num_pos * (float)BB);
    }
}

extern "C" void kernel_launch(void* const* d_in, const int* in_sizes, int n_in,
                              void* d_out, int out_size) {
    const float* pred = (const float*)d_in[0];  // [B, N, 5]
    const float* gt   = (const float*)d_in[1];  // [B, M, 4]
    float* out = (float*)d_out;

    kib_init_bins<<<BB, NBIN>>>(gt);
    dim3 gb(NN / (KB_THREADS * KB_T), BB);
    kb_main<<<gb, KB_THREADS>>>(pred, gt);
    k2_fixup<<<BB, MM>>>(pred, gt);
    k4_final<<<1, 32>>>(out);
}